// round 7
// baseline (speedup 1.0000x reference)
#include <cuda_runtime.h>

#define BB 512
#define LL 1024
#define DD 16
#define HH 64
#define G3 192      // 3*H
#define NB 7        // sequences per CTA
#define NTHREADS 512
#define NMV 384     // matvec threads: 192 rows x 2 half-rows
#define NCTA_PER_DIR 74   // ceil(512/7)

// scratch for y_f (offset 0) and y_b (offset B*L) — static device global (no alloc)
__device__ float g_scratch[2 * BB * LL];

__device__ __forceinline__ void fma2(unsigned long long &acc,
                                     unsigned long long a, unsigned long long b) {
    asm("fma.rn.f32x2 %0, %1, %2, %0;" : "+l"(acc) : "l"(a), "l"(b));
}
__device__ __forceinline__ float unpack_sum(unsigned long long v) {
    float lo, hi;
    asm("mov.b64 {%0, %1}, %2;" : "=f"(lo), "=f"(hi) : "l"(v));
    return lo + hi;
}
__device__ __forceinline__ float sigmoidf_(float x) {
    return 1.0f / (1.0f + __expf(-x));
}
__device__ __forceinline__ float tanhf_(float x) {
    float ax = fabsf(x);
    float e  = __expf(2.0f * ax);          // inf-safe: e=inf -> t=1
    float t  = 1.0f - 2.0f / (e + 1.0f);
    return copysignf(t, x);
}

__global__ __launch_bounds__(NTHREADS, 1)
void brios_main_kernel(
    const float* __restrict__ x,  const float* __restrict__ dt,
    const float* __restrict__ f_Wih, const float* __restrict__ f_Whh,
    const float* __restrict__ f_bih, const float* __restrict__ f_bhh,
    const float* __restrict__ f_gamma, const float* __restrict__ f_Wout,
    const float* __restrict__ f_bout,
    const float* __restrict__ b_Wih, const float* __restrict__ b_Whh,
    const float* __restrict__ b_bih, const float* __restrict__ b_bhh,
    const float* __restrict__ b_gamma, const float* __restrict__ b_Wout,
    const float* __restrict__ b_bout)
{
    __shared__ __align__(16) float h_sh[NB][HH];
    __shared__ __align__(16) float x_sh[NB][DD];
    __shared__ float gi_sh[NB][G3];
    __shared__ float gh_sh[NB][G3];
    __shared__ float decay_sh[NB];
    __shared__ float ypart[NB][2];

    const int tid  = threadIdx.x;
    const int dir  = blockIdx.x / NCTA_PER_DIR;   // 0 = forward, 1 = backward
    const int tile = blockIdx.x % NCTA_PER_DIR;
    const int b0   = tile * NB;

    const float* Wih  = dir ? b_Wih  : f_Wih;
    const float* Whh  = dir ? b_Whh  : f_Whh;
    const float* bih  = dir ? b_bih  : f_bih;
    const float* bhh  = dir ? b_bhh  : f_bhh;
    const float* Wout = dir ? b_Wout : f_Wout;
    const float  bout0 = dir ? b_bout[0] : f_bout[0];
    float g = dir ? b_gamma[0] : f_gamma[0];
    g = fminf(fmaxf(g, 1e-4f), 10.0f);

    float* yout = g_scratch + dir * (BB * LL);

    // ---- per-thread resident weights ----
    // matvec threads (tid < 384): half-row of Whh (32 floats -> 16 packed)
    unsigned long long whh2[HH / 4];
    float bhh_j = 0.0f;
    int mv_row = 0, mv_half = 0;
    // gi threads (tid >= 384): up to 2 Wih rows
    unsigned long long wih2[2][DD / 2];
    float bih2[2] = {0.f, 0.f};
    int gi_row0 = 0, gi_nrows = 0;

    if (tid < NMV) {
        mv_row  = tid >> 1;
        mv_half = tid & 1;
        const unsigned long long* p =
            reinterpret_cast<const unsigned long long*>(Whh + mv_row * HH + mv_half * 32);
        #pragma unroll
        for (int k = 0; k < HH / 4; k++) whh2[k] = p[k];
        bhh_j = bhh[mv_row];
    } else {
        int m2 = tid - NMV;           // 0..127
        gi_row0 = m2;
        gi_nrows = (m2 < 64) ? 2 : 1; // m2<64 also handles row 128+m2
        #pragma unroll
        for (int r = 0; r < 2; r++) {
            int row = (r == 0) ? m2 : (128 + m2);
            if (r < gi_nrows) {
                const unsigned long long* p =
                    reinterpret_cast<const unsigned long long*>(Wih + row * DD);
                #pragma unroll
                for (int k = 0; k < DD / 2; k++) wih2[r][k] = p[k];
                bih2[r] = bih[row];
            }
        }
    }
    const float wout_u = Wout[tid & (HH - 1)];

    // zero h
    for (int i = tid; i < NB * HH; i += NTHREADS) ((float*)h_sh)[i] = 0.0f;

    // initial prefetch (step t = 0)
    float xr = 0.0f, dtr = 0.0f;
    {
        int t0 = dir ? (LL - 1) : 0;
        if (tid < NB * DD) {
            int s = tid / DD, d = tid % DD;
            int bb = min(b0 + s, BB - 1);
            xr = x[(bb * LL + t0) * DD + d];
        }
        if (tid < NB) {
            int bb = min(b0 + tid, BB - 1);
            dtr = dt[bb * LL + t0];
        }
    }

    for (int t = 0; t < LL; t++) {
        __syncthreads();   // S1: order gate(t-1) writes (h_sh, ypart) before stage

        // ---- stage: publish x/dt regs, emit y(t-1), compute decay ----
        if (tid < NB * DD) {
            int s = tid / DD, d = tid % DD;
            x_sh[s][d] = xr;
        }
        if (tid < NB) {
            int s = tid;
            if (t > 0) {
                int b = b0 + s;
                if (b < BB) {
                    int tprev = dir ? (LL - t) : (t - 1);   // time index of step t-1
                    yout[b * LL + tprev] = ypart[s][0] + ypart[s][1] + bout0;
                }
            }
            float dc = fminf(fmaxf(dtr, 0.0f), 1.0e6f);
            decay_sh[s] = __expf(-g * dc);
        }
        __syncthreads();   // S2

        // ---- prefetch t+1 (latency hidden behind matvec) ----
        {
            int tn  = (t + 1 < LL) ? (t + 1) : (LL - 1);
            int ttn = dir ? (LL - 1 - tn) : tn;
            if (tid < NB * DD) {
                int s = tid / DD, d = tid % DD;
                int bb = min(b0 + s, BB - 1);
                xr = x[(bb * LL + ttn) * DD + d];
            }
            if (tid < NB) {
                int bb = min(b0 + tid, BB - 1);
                dtr = dt[bb * LL + ttn];
            }
        }

        // ---- matvec: gh = decay * (Whh . h) + bhh  /  gi = Wih . x + bih ----
        if (tid < NMV) {
            unsigned long long acc[NB];
            #pragma unroll
            for (int s = 0; s < NB; s++) acc[s] = 0ull;
            #pragma unroll
            for (int kp = 0; kp < 8; kp++) {             // 8 x 16B = 32 floats (half-row)
                #pragma unroll
                for (int s = 0; s < NB; s++) {
                    ulonglong2 hh = reinterpret_cast<const ulonglong2*>(
                        h_sh[s] + mv_half * 32)[kp];
                    fma2(acc[s], whh2[2 * kp],     hh.x);
                    fma2(acc[s], whh2[2 * kp + 1], hh.y);
                }
            }
            #pragma unroll
            for (int s = 0; s < NB; s++) {
                float v = unpack_sum(acc[s]);
                float o = __shfl_xor_sync(0xffffffffu, v, 1);
                if (mv_half == 0)
                    gh_sh[s][mv_row] = fmaf(decay_sh[s], v + o, bhh_j);
            }
        } else {
            #pragma unroll
            for (int s = 0; s < NB; s++) {
                ulonglong2 xv[4];
                #pragma unroll
                for (int q = 0; q < 4; q++)
                    xv[q] = reinterpret_cast<const ulonglong2*>(x_sh[s])[q];
                #pragma unroll
                for (int r = 0; r < 2; r++) {
                    if (r < gi_nrows) {
                        unsigned long long acc = 0ull;
                        #pragma unroll
                        for (int q = 0; q < 4; q++) {
                            fma2(acc, wih2[r][2 * q],     xv[q].x);
                            fma2(acc, wih2[r][2 * q + 1], xv[q].y);
                        }
                        int row = (r == 0) ? gi_row0 : (128 + gi_row0);
                        gi_sh[s][row] = unpack_sum(acc) + bih2[r];
                    }
                }
            }
        }
        __syncthreads();   // S3

        // ---- gate math + h update + fused y reduction ----
        if (tid < NB * HH) {
            int s = tid >> 6;
            int u = tid & (HH - 1);
            float hb = h_sh[s][u] * decay_sh[s];
            float r  = sigmoidf_(gi_sh[s][u]          + gh_sh[s][u]);
            float z  = sigmoidf_(gi_sh[s][HH + u]     + gh_sh[s][HH + u]);
            float n  = tanhf_   (gi_sh[s][2 * HH + u] + r * gh_sh[s][2 * HH + u]);
            float hnew = (1.0f - z) * n + z * hb;
            h_sh[s][u] = hnew;
            float c = hnew * wout_u;
            #pragma unroll
            for (int o = 16; o > 0; o >>= 1)
                c += __shfl_down_sync(0xffffffffu, c, o);
            if ((tid & 31) == 0)
                ypart[s][u >> 5] = c;
        }
    }

    // final y (step t = L-1)
    __syncthreads();
    if (tid < NB) {
        int b = b0 + tid;
        if (b < BB) {
            int tlast = dir ? 0 : (LL - 1);
            yout[b * LL + tlast] = ypart[tid][0] + ypart[tid][1] + bout0;
        }
    }
}

__global__ void brios_combine_kernel(float* __restrict__ out, int full) {
    int i = blockIdx.x * blockDim.x + threadIdx.x;
    const int n = BB * LL;
    if (i < n) {
        float a = g_scratch[i];          // y_f
        float b = g_scratch[n + i];      // y_b
        out[i] = 0.5f * (a + b);
        if (full) {
            out[n + i]     = a;
            out[2 * n + i] = b;
        }
    }
}

extern "C" void kernel_launch(void* const* d_in, const int* in_sizes, int n_in,
                              void* d_out, int out_size) {
    const float* x       = (const float*)d_in[0];
    const float* dt      = (const float*)d_in[1];
    const float* f_Wih   = (const float*)d_in[2];
    const float* f_Whh   = (const float*)d_in[3];
    const float* f_bih   = (const float*)d_in[4];
    const float* f_bhh   = (const float*)d_in[5];
    const float* f_gamma = (const float*)d_in[6];
    const float* f_Wout  = (const float*)d_in[7];
    const float* f_bout  = (const float*)d_in[8];
    const float* b_Wih   = (const float*)d_in[9];
    const float* b_Whh   = (const float*)d_in[10];
    const float* b_bih   = (const float*)d_in[11];
    const float* b_bhh   = (const float*)d_in[12];
    const float* b_gamma = (const float*)d_in[13];
    const float* b_Wout  = (const float*)d_in[14];
    const float* b_bout  = (const float*)d_in[15];
    float* out = (float*)d_out;

    brios_main_kernel<<<2 * NCTA_PER_DIR, NTHREADS>>>(
        x, dt,
        f_Wih, f_Whh, f_bih, f_bhh, f_gamma, f_Wout, f_bout,
        b_Wih, b_Whh, b_bih, b_bhh, b_gamma, b_Wout, b_bout);

    const int n = BB * LL;
    int full = (out_size >= 3 * n) ? 1 : 0;
    brios_combine_kernel<<<(n + 255) / 256, 256>>>(out, full);
}

// round 9
// speedup vs baseline: 1.1325x; 1.1325x over previous
#include <cuda_runtime.h>

#define BB 512
#define LL 1024
#define DD 16
#define HH 64
#define G3 192      // 3*H
#define NB 4        // sequences per CTA
#define NTHREADS 256
#define NMV 192     // matvec threads (one full Whh row each)
#define NCTA_PER_DIR 148  // 148 tiles of 4 -> 592 slots >= 512 (2 CTAs/SM exactly)

// scratch for y_f (offset 0) and y_b (offset B*L) — static device global (no alloc)
__device__ float g_scratch[2 * BB * LL];

__device__ __forceinline__ void fma2(unsigned long long &acc,
                                     unsigned long long a, unsigned long long b) {
    asm("fma.rn.f32x2 %0, %1, %2, %0;" : "+l"(acc) : "l"(a), "l"(b));
}
__device__ __forceinline__ float unpack_sum(unsigned long long v) {
    float lo, hi;
    asm("mov.b64 {%0, %1}, %2;" : "=f"(lo), "=f"(hi) : "l"(v));
    return lo + hi;
}
__device__ __forceinline__ float sigmoidf_(float x) {
    return 1.0f / (1.0f + __expf(-x));
}
__device__ __forceinline__ float tanhf_(float x) {
    float ax = fabsf(x);
    float e  = __expf(2.0f * ax);          // inf-safe: e=inf -> t=1
    float t  = 1.0f - 2.0f / (e + 1.0f);
    return copysignf(t, x);
}

__global__ __launch_bounds__(NTHREADS, 2)
void brios_main_kernel(
    const float* __restrict__ x,  const float* __restrict__ dt,
    const float* __restrict__ f_Wih, const float* __restrict__ f_Whh,
    const float* __restrict__ f_bih, const float* __restrict__ f_bhh,
    const float* __restrict__ f_gamma, const float* __restrict__ f_Wout,
    const float* __restrict__ f_bout,
    const float* __restrict__ b_Wih, const float* __restrict__ b_Whh,
    const float* __restrict__ b_bih, const float* __restrict__ b_bhh,
    const float* __restrict__ b_gamma, const float* __restrict__ b_Wout,
    const float* __restrict__ b_bout)
{
    __shared__ __align__(16) float h_sh[NB][HH];
    __shared__ __align__(16) float x_sh[NB][DD];
    __shared__ float gi_sh[NB][G3];
    __shared__ float gh_sh[NB][G3];
    __shared__ float decay_sh[NB];
    __shared__ float ypart[NB][2];

    const int tid  = threadIdx.x;
    const int dir  = blockIdx.x / NCTA_PER_DIR;   // 0 = forward, 1 = backward
    const int tile = blockIdx.x % NCTA_PER_DIR;
    const int b0   = tile * NB;

    const float* Wih  = dir ? b_Wih  : f_Wih;
    const float* Whh  = dir ? b_Whh  : f_Whh;
    const float* bih  = dir ? b_bih  : f_bih;
    const float* bhh  = dir ? b_bhh  : f_bhh;
    const float* Wout = dir ? b_Wout : f_Wout;
    const float  bout0 = dir ? b_bout[0] : f_bout[0];
    float g = dir ? b_gamma[0] : f_gamma[0];
    g = fminf(fmaxf(g, 1e-4f), 10.0f);

    float* yout = g_scratch + dir * (BB * LL);

    // ---- per-thread resident weights ----
    // matvec threads (tid < 192): one full Whh row (64 floats -> 32 packed f32x2)
    unsigned long long whh2[HH / 2];
    float bhh_j = 0.0f;
    // gi threads (tid >= 192): row triplet {u, 64+u, 128+u} of Wih
    unsigned long long wih2[3][DD / 2];
    float bih3[3] = {0.f, 0.f, 0.f};

    if (tid < NMV) {
        const unsigned long long* p =
            reinterpret_cast<const unsigned long long*>(Whh + tid * HH);
        #pragma unroll
        for (int k = 0; k < HH / 2; k++) whh2[k] = p[k];
        bhh_j = bhh[tid];
    } else {
        int u = tid - NMV;            // 0..63
        #pragma unroll
        for (int r = 0; r < 3; r++) {
            int row = u + r * HH;
            const unsigned long long* p =
                reinterpret_cast<const unsigned long long*>(Wih + row * DD);
            #pragma unroll
            for (int k = 0; k < DD / 2; k++) wih2[r][k] = p[k];
            bih3[r] = bih[row];
        }
    }
    const float wout_u = Wout[tid & (HH - 1)];

    // zero h
    for (int i = tid; i < NB * HH; i += NTHREADS) ((float*)h_sh)[i] = 0.0f;

    // initial prefetch (step t = 0)
    float xr = 0.0f, dtr = 0.0f;
    {
        int t0 = dir ? (LL - 1) : 0;
        if (tid < NB * DD) {
            int s = tid / DD, d = tid % DD;
            int bb = min(b0 + s, BB - 1);
            xr = x[(bb * LL + t0) * DD + d];
        }
        if (tid < NB) {
            int bb = min(b0 + tid, BB - 1);
            dtr = dt[bb * LL + t0];
        }
    }

    for (int t = 0; t < LL; t++) {
        __syncthreads();   // S1: order gate(t-1) writes (h_sh, ypart) before stage

        // ---- stage: publish x/dt regs, emit y(t-1), compute decay ----
        if (tid < NB * DD) {
            int s = tid / DD, d = tid % DD;
            x_sh[s][d] = xr;
        }
        if (tid < NB) {
            int s = tid;
            if (t > 0) {
                int b = b0 + s;
                if (b < BB) {
                    int tprev = dir ? (LL - t) : (t - 1);   // time index of step t-1
                    yout[b * LL + tprev] = ypart[s][0] + ypart[s][1] + bout0;
                }
            }
            float dc = fminf(fmaxf(dtr, 0.0f), 1.0e6f);
            decay_sh[s] = __expf(-g * dc);
        }
        __syncthreads();   // S2

        // ---- prefetch t+1 (latency hidden behind matvec) ----
        {
            int tn  = (t + 1 < LL) ? (t + 1) : (LL - 1);
            int ttn = dir ? (LL - 1 - tn) : tn;
            if (tid < NB * DD) {
                int s = tid / DD, d = tid % DD;
                int bb = min(b0 + s, BB - 1);
                xr = x[(bb * LL + ttn) * DD + d];
            }
            if (tid < NB) {
                int bb = min(b0 + tid, BB - 1);
                dtr = dt[bb * LL + ttn];
            }
        }

        // ---- matvec: gh = decay * (Whh . h) + bhh  /  gi = Wih . x + bih ----
        if (tid < NMV) {
            unsigned long long acc[NB];
            #pragma unroll
            for (int s = 0; s < NB; s++) acc[s] = 0ull;
            #pragma unroll
            for (int kp = 0; kp < HH / 4; kp++) {
                #pragma unroll
                for (int s = 0; s < NB; s++) {
                    ulonglong2 hh =
                        reinterpret_cast<const ulonglong2*>(h_sh[s])[kp];
                    fma2(acc[s], whh2[2 * kp],     hh.x);
                    fma2(acc[s], whh2[2 * kp + 1], hh.y);
                }
            }
            #pragma unroll
            for (int s = 0; s < NB; s++)
                gh_sh[s][tid] = fmaf(decay_sh[s], unpack_sum(acc[s]), bhh_j);
        } else {
            int u = tid - NMV;
            #pragma unroll
            for (int s = 0; s < NB; s++) {
                ulonglong2 xv[4];
                #pragma unroll
                for (int q = 0; q < 4; q++)
                    xv[q] = reinterpret_cast<const ulonglong2*>(x_sh[s])[q];
                #pragma unroll
                for (int r = 0; r < 3; r++) {
                    unsigned long long acc = 0ull;
                    #pragma unroll
                    for (int q = 0; q < 4; q++) {
                        fma2(acc, wih2[r][2 * q],     xv[q].x);
                        fma2(acc, wih2[r][2 * q + 1], xv[q].y);
                    }
                    gi_sh[s][u + r * HH] = unpack_sum(acc) + bih3[r];
                }
            }
        }
        __syncthreads();   // S3

        // ---- gate math + h update + fused y reduction (all 256 threads) ----
        {
            int s = tid >> 6;            // 0..3
            int u = tid & (HH - 1);      // 0..63
            float hb = h_sh[s][u] * decay_sh[s];
            float r  = sigmoidf_(gi_sh[s][u]          + gh_sh[s][u]);
            float z  = sigmoidf_(gi_sh[s][HH + u]     + gh_sh[s][HH + u]);
            float n  = tanhf_   (gi_sh[s][2 * HH + u] + r * gh_sh[s][2 * HH + u]);
            float hnew = (1.0f - z) * n + z * hb;
            h_sh[s][u] = hnew;
            float c = hnew * wout_u;
            #pragma unroll
            for (int o = 16; o > 0; o >>= 1)
                c += __shfl_down_sync(0xffffffffu, c, o);
            if ((tid & 31) == 0)
                ypart[s][u >> 5] = c;
        }
    }

    // final y (step t = L-1)
    __syncthreads();
    if (tid < NB) {
        int b = b0 + tid;
        if (b < BB) {
            int tlast = dir ? 0 : (LL - 1);
            yout[b * LL + tlast] = ypart[tid][0] + ypart[tid][1] + bout0;
        }
    }
}

__global__ void brios_combine_kernel(float* __restrict__ out, int full) {
    int i = blockIdx.x * blockDim.x + threadIdx.x;
    const int n = BB * LL;
    if (i < n) {
        float a = g_scratch[i];          // y_f
        float b = g_scratch[n + i];      // y_b
        out[i] = 0.5f * (a + b);
        if (full) {
            out[n + i]     = a;
            out[2 * n + i] = b;
        }
    }
}

extern "C" void kernel_launch(void* const* d_in, const int* in_sizes, int n_in,
                              void* d_out, int out_size) {
    const float* x       = (const float*)d_in[0];
    const float* dt      = (const float*)d_in[1];
    const float* f_Wih   = (const float*)d_in[2];
    const float* f_Whh   = (const float*)d_in[3];
    const float* f_bih   = (const float*)d_in[4];
    const float* f_bhh   = (const float*)d_in[5];
    const float* f_gamma = (const float*)d_in[6];
    const float* f_Wout  = (const float*)d_in[7];
    const float* f_bout  = (const float*)d_in[8];
    const float* b_Wih   = (const float*)d_in[9];
    const float* b_Whh   = (const float*)d_in[10];
    const float* b_bih   = (const float*)d_in[11];
    const float* b_bhh   = (const float*)d_in[12];
    const float* b_gamma = (const float*)d_in[13];
    const float* b_Wout  = (const float*)d_in[14];
    const float* b_bout  = (const float*)d_in[15];
    float* out = (float*)d_out;

    brios_main_kernel<<<2 * NCTA_PER_DIR, NTHREADS>>>(
        x, dt,
        f_Wih, f_Whh, f_bih, f_bhh, f_gamma, f_Wout, f_bout,
        b_Wih, b_Whh, b_bih, b_bhh, b_gamma, b_Wout, b_bout);

    const int n = BB * LL;
    int full = (out_size >= 3 * n) ? 1 : 0;
    brios_combine_kernel<<<(n + 255) / 256, 256>>>(out, full);
}

// round 10
// speedup vs baseline: 1.2971x; 1.1454x over previous
#include <cuda_runtime.h>

#define BB 512
#define LL 1024
#define DD 16
#define HH 64
#define G3 192      // 3*H
#define NB 7        // sequences per CTA
#define NTHREADS 256
#define NMV 192     // matvec threads (one full Whh row each)
#define NCTA_PER_DIR 74   // ceil(512/7) -> 148 CTAs total = 1/SM

// scratch for y_f (offset 0) and y_b (offset B*L) — static device global (no alloc)
__device__ float g_scratch[2 * BB * LL];

__device__ __forceinline__ void fma2(unsigned long long &acc,
                                     unsigned long long a, unsigned long long b) {
    asm("fma.rn.f32x2 %0, %1, %2, %0;" : "+l"(acc) : "l"(a), "l"(b));
}
__device__ __forceinline__ float unpack_sum(unsigned long long v) {
    float lo, hi;
    asm("mov.b64 {%0, %1}, %2;" : "=f"(lo), "=f"(hi) : "l"(v));
    return lo + hi;
}
__device__ __forceinline__ float sigmoidf_(float x) {
    return 1.0f / (1.0f + __expf(-x));
}
__device__ __forceinline__ float tanhf_(float x) {
    float ax = fabsf(x);
    float e  = __expf(2.0f * ax);          // inf-safe: e=inf -> t=1
    float t  = 1.0f - 2.0f / (e + 1.0f);
    return copysignf(t, x);
}

__global__ void brios_dummy_kernel() {}   // ncu launch-skip alignment

__global__ __launch_bounds__(NTHREADS, 1)
void brios_main_kernel(
    const float* __restrict__ x,  const float* __restrict__ dt,
    const float* __restrict__ f_Wih, const float* __restrict__ f_Whh,
    const float* __restrict__ f_bih, const float* __restrict__ f_bhh,
    const float* __restrict__ f_gamma, const float* __restrict__ f_Wout,
    const float* __restrict__ f_bout,
    const float* __restrict__ b_Wih, const float* __restrict__ b_Whh,
    const float* __restrict__ b_bih, const float* __restrict__ b_bhh,
    const float* __restrict__ b_gamma, const float* __restrict__ b_Wout,
    const float* __restrict__ b_bout)
{
    __shared__ __align__(16) float h_sh[NB][HH];
    __shared__ __align__(16) float x_sh[NB][DD];
    __shared__ float gi_sh[NB][G3];
    __shared__ float gh_sh[NB][G3];
    __shared__ float decay_sh[2][NB];
    __shared__ __align__(16) float ypart[2][NB][8];

    const int tid  = threadIdx.x;
    const int dir  = blockIdx.x / NCTA_PER_DIR;   // 0 = forward, 1 = backward
    const int tile = blockIdx.x % NCTA_PER_DIR;
    const int b0   = tile * NB;

    const float* Wih  = dir ? b_Wih  : f_Wih;
    const float* Whh  = dir ? b_Whh  : f_Whh;
    const float* bih  = dir ? b_bih  : f_bih;
    const float* bhh  = dir ? b_bhh  : f_bhh;
    const float* Wout = dir ? b_Wout : f_Wout;
    const float  bout0 = dir ? b_bout[0] : f_bout[0];
    float g = dir ? b_gamma[0] : f_gamma[0];
    g = fminf(fmaxf(g, 1e-4f), 10.0f);

    float* yout = g_scratch + dir * (BB * LL);

    // ---- per-thread resident weights ----
    unsigned long long whh2[HH / 2];   // matvec threads (tid < 192): one Whh row
    float bhh_j = 0.0f;
    unsigned long long wih2[3][DD / 2]; // gi threads (tid >= 192): 3 Wih rows
    float bih3[3] = {0.f, 0.f, 0.f};

    if (tid < NMV) {
        const unsigned long long* p =
            reinterpret_cast<const unsigned long long*>(Whh + tid * HH);
        #pragma unroll
        for (int k = 0; k < HH / 2; k++) whh2[k] = p[k];
        bhh_j = bhh[tid];
    } else {
        int u = tid - NMV;            // 0..63
        #pragma unroll
        for (int r = 0; r < 3; r++) {
            int row = u + r * HH;
            const unsigned long long* p =
                reinterpret_cast<const unsigned long long*>(Wih + row * DD);
            #pragma unroll
            for (int k = 0; k < DD / 2; k++) wih2[r][k] = p[k];
            bih3[r] = bih[row];
        }
    }
    const float wout_u = Wout[tid & (HH - 1)];

    // zero h
    for (int i = tid; i < NB * HH; i += NTHREADS) ((float*)h_sh)[i] = 0.0f;

    // ---- prologue: publish x(0), decay(0); prefetch t=1 into regs ----
    float xr = 0.0f, dtr = 0.0f;
    {
        int t0 = dir ? (LL - 1) : 0;
        if (tid < NB * DD) {
            int s = tid / DD, d = tid % DD;
            int bb = min(b0 + s, BB - 1);
            x_sh[s][d] = x[(bb * LL + t0) * DD + d];
        }
        if (tid < NB) {
            int bb = min(b0 + tid, BB - 1);
            float dc = fminf(fmaxf(dt[bb * LL + t0], 0.0f), 1.0e6f);
            decay_sh[0][tid] = __expf(-g * dc);
        }
        int t1  = (LL > 1) ? 1 : 0;
        int tt1 = dir ? (LL - 1 - t1) : t1;
        if (tid < NB * DD) {
            int s = tid / DD, d = tid % DD;
            int bb = min(b0 + s, BB - 1);
            xr = x[(bb * LL + tt1) * DD + d];
        }
        if (tid < NB) {
            int bb = min(b0 + tid, BB - 1);
            dtr = dt[bb * LL + tt1];
        }
    }
    __syncthreads();

    for (int t = 0; t < LL; t++) {
        const int cb = t & 1;
        const int pb = cb ^ 1;

        // ================= phase A: matvec =================
        if (tid < NMV) {
            unsigned long long acc[NB];
            #pragma unroll
            for (int s = 0; s < NB; s++) acc[s] = 0ull;
            #pragma unroll
            for (int kp = 0; kp < HH / 4; kp++) {
                #pragma unroll
                for (int s = 0; s < NB; s++) {
                    ulonglong2 hh =
                        reinterpret_cast<const ulonglong2*>(h_sh[s])[kp];
                    fma2(acc[s], whh2[2 * kp],     hh.x);
                    fma2(acc[s], whh2[2 * kp + 1], hh.y);
                }
            }
            #pragma unroll
            for (int s = 0; s < NB; s++)
                gh_sh[s][tid] = fmaf(decay_sh[cb][s], unpack_sum(acc[s]), bhh_j);
        } else {
            int u = tid - NMV;
            #pragma unroll
            for (int s = 0; s < NB; s++) {
                ulonglong2 xv[4];
                #pragma unroll
                for (int q = 0; q < 4; q++)
                    xv[q] = reinterpret_cast<const ulonglong2*>(x_sh[s])[q];
                #pragma unroll
                for (int r = 0; r < 3; r++) {
                    unsigned long long acc = 0ull;
                    #pragma unroll
                    for (int q = 0; q < 4; q++) {
                        fma2(acc, wih2[r][2 * q],     xv[q].x);
                        fma2(acc, wih2[r][2 * q + 1], xv[q].y);
                    }
                    gi_sh[s][u + r * HH] = unpack_sum(acc) + bih3[r];
                }
            }
        }
        __syncthreads();

        // ================= phase B: stage(t+1) + gate(t) =================
        // stage: publish x(t+1), emit y(t-1), decay(t+1); prefetch t+2
        if (tid < NB * DD) {
            int s = tid / DD, d = tid % DD;
            x_sh[s][d] = xr;                         // x for step t+1
        }
        if (tid < NB) {
            if (t > 0) {
                int b = b0 + tid;
                if (b < BB) {
                    int tprev = dir ? (LL - t) : (t - 1);
                    const float4* yp =
                        reinterpret_cast<const float4*>(ypart[pb][tid]);
                    float4 a = yp[0], c = yp[1];
                    yout[b * LL + tprev] =
                        a.x + a.y + a.z + a.w + c.x + c.y + c.z + c.w + bout0;
                }
            }
            float dc = fminf(fmaxf(dtr, 0.0f), 1.0e6f);
            decay_sh[pb][tid] = __expf(-g * dc);     // decay for step t+1
        }
        {
            int tn  = (t + 2 < LL) ? (t + 2) : (LL - 1);
            int ttn = dir ? (LL - 1 - tn) : tn;
            if (tid < NB * DD) {
                int s = tid / DD, d = tid % DD;
                int bb = min(b0 + s, BB - 1);
                xr = x[(bb * LL + ttn) * DD + d];
            }
            if (tid < NB) {
                int bb = min(b0 + tid, BB - 1);
                dtr = dt[bb * LL + ttn];
            }
        }

        // gate: 448 items over 256 threads (2 iterations); u == tid&63 both iters
        const int u = tid & (HH - 1);
        #pragma unroll
        for (int iter = 0; iter < 2; iter++) {
            int idx = tid + iter * NTHREADS;
            if (idx < NB * HH) {
                int s = idx >> 6;
                float dk = decay_sh[cb][s];
                float hb = h_sh[s][u] * dk;
                float r  = sigmoidf_(gi_sh[s][u]          + gh_sh[s][u]);
                float z  = sigmoidf_(gi_sh[s][HH + u]     + gh_sh[s][HH + u]);
                float n  = tanhf_   (gi_sh[s][2 * HH + u] + r * gh_sh[s][2 * HH + u]);
                float hnew = (1.0f - z) * n + z * hb;
                h_sh[s][u] = hnew;
                float c = hnew * wout_u;
                c += __shfl_down_sync(0xffffffffu, c, 16);
                c += __shfl_down_sync(0xffffffffu, c, 8);
                c += __shfl_down_sync(0xffffffffu, c, 4);
                if ((u & 31) < 4)
                    ypart[cb][s][(u >> 5) * 4 + (u & 3)] = c;
            }
        }
        __syncthreads();
    }

    // final y (step t = L-1); last barrier already executed
    if (tid < NB) {
        int b = b0 + tid;
        if (b < BB) {
            int tlast = dir ? 0 : (LL - 1);
            const float4* yp =
                reinterpret_cast<const float4*>(ypart[(LL - 1) & 1][tid]);
            float4 a = yp[0], c = yp[1];
            yout[b * LL + tlast] =
                a.x + a.y + a.z + a.w + c.x + c.y + c.z + c.w + bout0;
        }
    }
}

__global__ void brios_combine_kernel(float* __restrict__ out, int full) {
    int i = blockIdx.x * blockDim.x + threadIdx.x;
    const int n = BB * LL;
    if (i < n) {
        float a = g_scratch[i];          // y_f
        float b = g_scratch[n + i];      // y_b
        out[i] = 0.5f * (a + b);
        if (full) {
            out[n + i]     = a;
            out[2 * n + i] = b;
        }
    }
}

extern "C" void kernel_launch(void* const* d_in, const int* in_sizes, int n_in,
                              void* d_out, int out_size) {
    const float* x       = (const float*)d_in[0];
    const float* dt      = (const float*)d_in[1];
    const float* f_Wih   = (const float*)d_in[2];
    const float* f_Whh   = (const float*)d_in[3];
    const float* f_bih   = (const float*)d_in[4];
    const float* f_bhh   = (const float*)d_in[5];
    const float* f_gamma = (const float*)d_in[6];
    const float* f_Wout  = (const float*)d_in[7];
    const float* f_bout  = (const float*)d_in[8];
    const float* b_Wih   = (const float*)d_in[9];
    const float* b_Whh   = (const float*)d_in[10];
    const float* b_bih   = (const float*)d_in[11];
    const float* b_bhh   = (const float*)d_in[12];
    const float* b_gamma = (const float*)d_in[13];
    const float* b_Wout  = (const float*)d_in[14];
    const float* b_bout  = (const float*)d_in[15];
    float* out = (float*)d_out;

    // 5 dummy launches: aligns ncu's "-s 5 -c 1" onto brios_main_kernel
    for (int i = 0; i < 5; i++) brios_dummy_kernel<<<1, 1>>>();

    brios_main_kernel<<<2 * NCTA_PER_DIR, NTHREADS>>>(
        x, dt,
        f_Wih, f_Whh, f_bih, f_bhh, f_gamma, f_Wout, f_bout,
        b_Wih, b_Whh, b_bih, b_bhh, b_gamma, b_Wout, b_bout);

    const int n = BB * LL;
    int full = (out_size >= 3 * n) ? 1 : 0;
    brios_combine_kernel<<<(n + 255) / 256, 256>>>(out, full);
}